// round 8
// baseline (speedup 1.0000x reference)
#include <cuda_runtime.h>
#include <cuda_bf16.h>
#include <cstdint>

// Problem constants
#define BATCH 512
#define DD 512
#define NITER 7
#define SPLITK 2
#define KPER (DD / SPLITK)      // 256 per CTA
#define BK 64                   // k-chunk staged in smem
#define APITCH 72               // padded smem pitch (bank-conflict-free ldmatrix)

// ---------------------------------------------------------------------------
// Scratch (device globals — no allocation allowed)
// ---------------------------------------------------------------------------
__device__ float g_r[BATCH * DD];
__device__ float g_p[BATCH * DD];
__device__ float g_y[BATCH * DD];
__device__ float g_qp[SPLITK][BATCH * DD];
__device__ __nv_bfloat16 g_c_hi[DD * DD];
__device__ __nv_bfloat16 g_c_lo[DD * DD];
__device__ float g_shift[BATCH];
__device__ float g_oscale[BATCH];
__device__ float g_rr[BATCH];

// ---------------------------------------------------------------------------
// PTX helpers (sm_80-era instructions only — safe for plain sm_103 ptxas)
// ---------------------------------------------------------------------------
__device__ __forceinline__ uint32_t smem_u32(const void* p) {
    uint32_t a;
    asm("{ .reg .u64 t; cvta.to.shared.u64 t, %1; cvt.u32.u64 %0, t; }"
        : "=r"(a) : "l"(p));
    return a;
}

__device__ __forceinline__ void ldsm4(uint32_t* r, uint32_t addr) {
    asm volatile("ldmatrix.sync.aligned.m8n8.x4.shared.b16 {%0,%1,%2,%3}, [%4];"
                 : "=r"(r[0]), "=r"(r[1]), "=r"(r[2]), "=r"(r[3]) : "r"(addr));
}

__device__ __forceinline__ void mma_bf16(float* d, const uint32_t* a,
                                         uint32_t b0, uint32_t b1) {
    asm volatile(
        "mma.sync.aligned.m16n8k16.row.col.f32.bf16.bf16.f32 "
        "{%0,%1,%2,%3}, {%4,%5,%6,%7}, {%8,%9}, {%0,%1,%2,%3};"
        : "+f"(d[0]), "+f"(d[1]), "+f"(d[2]), "+f"(d[3])
        : "r"(a[0]), "r"(a[1]), "r"(a[2]), "r"(a[3]), "r"(b0), "r"(b1));
}

__device__ __forceinline__ float warp_sum(float v) {
#pragma unroll
    for (int m = 16; m > 0; m >>= 1)
        v += __shfl_xor_sync(0xFFFFFFFFu, v, m);
    return v;
}

// ---------------------------------------------------------------------------
// Init: per-batch scalars, rhs = exp(0.5 B) x - mu ; r = p = rhs ; y = 0 ;
// rr = ||rhs||^2
// ---------------------------------------------------------------------------
__global__ __launch_bounds__(256) void init_kernel(const float* __restrict__ x,
                                                   const float* __restrict__ t,
                                                   const float* __restrict__ mu) {
    int b = blockIdx.x;
    int tid = threadIdx.x;
    float tv = t[b];
    float B = 9.95f * tv * tv + 0.1f * tv;
    float eh = expf(0.5f * B);
    float shift = expm1f(B);
    float rescale = sqrtf(-expm1f(-B));
    if (tid == 0) {
        g_shift[b] = shift;
        g_oscale[b] = -(eh * rescale);
    }
    float acc = 0.0f;
    __shared__ float sred[256];
#pragma unroll
    for (int k = 0; k < 2; k++) {
        int i = b * DD + tid + k * 256;
        float v = eh * x[i] - mu[tid + k * 256];
        g_r[i] = v;
        g_p[i] = v;
        g_y[i] = 0.0f;
        acc += v * v;
    }
    sred[tid] = acc;
    __syncthreads();
    for (int s = 128; s > 0; s >>= 1) {
        if (tid < s) sred[tid] += sred[tid + s];
        __syncthreads();
    }
    if (tid == 0) g_rr[b] = sred[0];
}

// ---------------------------------------------------------------------------
// Prep C: bf16 hi/lo split of posterior_cov (symmetric: row n == col n)
// ---------------------------------------------------------------------------
__global__ __launch_bounds__(256) void prep_c_kernel(const float* __restrict__ cov) {
    int i = blockIdx.x;
    int tid = threadIdx.x;
#pragma unroll
    for (int k = 0; k < 2; k++) {
        int idx = i * DD + tid + k * 256;
        float v = cov[idx];
        __nv_bfloat16 h = __float2bfloat16(v);
        g_c_hi[idx] = h;
        g_c_lo[idx] = __float2bfloat16(v - __bfloat162float(h));
    }
}

// ---------------------------------------------------------------------------
// mma.sync GEMM: qp[kz][m][n] = sum_{k in slice} p[m][k] * C[n][k]
// A (p) staged from fp32 with on-the-fly hi/lo bf16 split; core loop unchanged.
// ---------------------------------------------------------------------------
__global__ __launch_bounds__(128) void gemm_mma_kernel() {
    __shared__ __nv_bfloat16 sAhi[64][APITCH];
    __shared__ __nv_bfloat16 sAlo[64][APITCH];
    __shared__ __nv_bfloat16 sBhi[64][APITCH];
    __shared__ __nv_bfloat16 sBlo[64][APITCH];

    const int tid = threadIdx.x;
    const int lid = tid & 31;
    const int wid = tid >> 5;
    const int wm = (wid & 1) * 32;
    const int wn = (wid >> 1) * 32;
    const int bm = blockIdx.y * 64;
    const int bn = blockIdx.x * 64;
    const int kbase = blockIdx.z * KPER;

    float acc[2][4][4];
#pragma unroll
    for (int i = 0; i < 2; i++)
#pragma unroll
        for (int j = 0; j < 4; j++)
#pragma unroll
            for (int v = 0; v < 4; v++) acc[i][j][v] = 0.0f;

    const int lrow = lid & 15;
    const int lcol8 = (lid >> 4) * 8;

    for (int kc = kbase; kc < kbase + KPER; kc += BK) {
        __syncthreads();
#pragma unroll
        for (int i = 0; i < 4; i++) {
            int slot = tid + 128 * i;
            int row = slot >> 3;
            int c8 = (slot & 7) * 8;
            // A: load 8 fp32 from g_p, split into hi/lo bf16
            const float4* ap = (const float4*)&g_p[(bm + row) * DD + kc + c8];
            float4 a0 = ap[0], a1 = ap[1];
            float av[8] = {a0.x, a0.y, a0.z, a0.w, a1.x, a1.y, a1.z, a1.w};
#pragma unroll
            for (int j = 0; j < 4; j++) {
                __nv_bfloat162 h2, l2;
                float v0 = av[j * 2], v1 = av[j * 2 + 1];
                h2.x = __float2bfloat16(v0);
                h2.y = __float2bfloat16(v1);
                l2.x = __float2bfloat16(v0 - __bfloat162float(h2.x));
                l2.y = __float2bfloat16(v1 - __bfloat162float(h2.y));
                *(__nv_bfloat162*)&sAhi[row][c8 + j * 2] = h2;
                *(__nv_bfloat162*)&sAlo[row][c8 + j * 2] = l2;
            }
            // B: bf16 hi/lo precomputed
            *(uint4*)&sBhi[row][c8] = *(const uint4*)&g_c_hi[(bn + row) * DD + kc + c8];
            *(uint4*)&sBlo[row][c8] = *(const uint4*)&g_c_lo[(bn + row) * DD + kc + c8];
        }
        __syncthreads();

#pragma unroll
        for (int ks = 0; ks < BK / 16; ks++) {
            int kk = ks * 16 + lcol8;
            uint32_t ahi[2][4], alo[2][4], bhi[2][4], blo[2][4];
#pragma unroll
            for (int mi = 0; mi < 2; mi++) {
                ldsm4(ahi[mi], smem_u32(&sAhi[wm + mi * 16 + lrow][kk]));
                ldsm4(alo[mi], smem_u32(&sAlo[wm + mi * 16 + lrow][kk]));
            }
#pragma unroll
            for (int nh = 0; nh < 2; nh++) {
                ldsm4(bhi[nh], smem_u32(&sBhi[wn + nh * 16 + lrow][kk]));
                ldsm4(blo[nh], smem_u32(&sBlo[wn + nh * 16 + lrow][kk]));
            }
#pragma unroll
            for (int mi = 0; mi < 2; mi++)
#pragma unroll
                for (int ni = 0; ni < 4; ni++) {
                    int nh = ni >> 1, sb = ni & 1;
                    mma_bf16(acc[mi][ni], ahi[mi], bhi[nh][sb], bhi[nh][sb + 2]);
                    mma_bf16(acc[mi][ni], ahi[mi], blo[nh][sb], blo[nh][sb + 2]);
                    mma_bf16(acc[mi][ni], alo[mi], bhi[nh][sb], bhi[nh][sb + 2]);
                }
        }
    }

    float* qp = g_qp[blockIdx.z];
    const int g = lid >> 2, tq = lid & 3;
#pragma unroll
    for (int mi = 0; mi < 2; mi++)
#pragma unroll
        for (int ni = 0; ni < 4; ni++) {
            int row = bm + wm + mi * 16 + g;
            int col = bn + wn + ni * 8 + tq * 2;
            *(float2*)&qp[row * DD + col] = make_float2(acc[mi][ni][0], acc[mi][ni][1]);
            *(float2*)&qp[(row + 8) * DD + col] = make_float2(acc[mi][ni][2], acc[mi][ni][3]);
        }
}

// ---------------------------------------------------------------------------
// CG update: 2 warps per row, 64 threads/row, 8 elems (2 float4) per thread.
// 4 rows per 256-thread block -> 128 blocks, 1024 warps chip-wide.
// Reductions: warp shfl + one smem combine (2 barriers per kernel).
// LAST=true: out = oscale*(y + alpha*p), skip the rest.
// ---------------------------------------------------------------------------
template <bool LAST>
__global__ __launch_bounds__(256) void cg_update_kernel(float* __restrict__ out) {
    const int tid = threadIdx.x;
    const int rl = tid >> 6;           // row within block (0..3)
    const int sub = tid & 63;          // thread within row
    const int w = (tid >> 5) & 1;      // warp within row
    const int b = blockIdx.x * 4 + rl;
    const float sh = g_shift[b];
    const int base = b * DD + sub * 8;

    __shared__ float sdot[4][2];
    __shared__ float srr[4][2];

    float4 p[2], q[2], r[2];
#pragma unroll
    for (int i = 0; i < 2; i++) {
        int idx = base + i * 4;
        p[i] = *(const float4*)&g_p[idx];
        float4 q0 = *(const float4*)&g_qp[0][idx];
        float4 q1 = *(const float4*)&g_qp[1][idx];
        q[i].x = q0.x + q1.x + sh * p[i].x;
        q[i].y = q0.y + q1.y + sh * p[i].y;
        q[i].z = q0.z + q1.z + sh * p[i].z;
        q[i].w = q0.w + q1.w + sh * p[i].w;
        if (!LAST) r[i] = *(const float4*)&g_r[idx];
    }

    float dot = 0.0f;
#pragma unroll
    for (int i = 0; i < 2; i++)
        dot += p[i].x * q[i].x + p[i].y * q[i].y + p[i].z * q[i].z + p[i].w * q[i].w;
    dot = warp_sum(dot);
    if ((tid & 31) == 0) sdot[rl][w] = dot;
    __syncthreads();
    float rro = g_rr[b];
    float alpha = rro / fmaxf(sdot[rl][0] + sdot[rl][1], 1e-30f);

    if (LAST) {
        float os = g_oscale[b];
#pragma unroll
        for (int i = 0; i < 2; i++) {
            int idx = base + i * 4;
            float4 y = *(const float4*)&g_y[idx];
            float4 o;
            o.x = os * (y.x + alpha * p[i].x);
            o.y = os * (y.y + alpha * p[i].y);
            o.z = os * (y.z + alpha * p[i].z);
            o.w = os * (y.w + alpha * p[i].w);
            *(float4*)&out[idx] = o;
        }
        return;
    }

    float rr_new = 0.0f;
#pragma unroll
    for (int i = 0; i < 2; i++) {
        int idx = base + i * 4;
        float4 y = *(const float4*)&g_y[idx];
        y.x += alpha * p[i].x; y.y += alpha * p[i].y;
        y.z += alpha * p[i].z; y.w += alpha * p[i].w;
        *(float4*)&g_y[idx] = y;
        r[i].x -= alpha * q[i].x; r[i].y -= alpha * q[i].y;
        r[i].z -= alpha * q[i].z; r[i].w -= alpha * q[i].w;
        *(float4*)&g_r[idx] = r[i];
        rr_new += r[i].x * r[i].x + r[i].y * r[i].y +
                  r[i].z * r[i].z + r[i].w * r[i].w;
    }
    rr_new = warp_sum(rr_new);
    if ((tid & 31) == 0) srr[rl][w] = rr_new;
    __syncthreads();
    rr_new = srr[rl][0] + srr[rl][1];
    float beta = rr_new / fmaxf(rro, 1e-30f);
    if (sub == 0) g_rr[b] = rr_new;

#pragma unroll
    for (int i = 0; i < 2; i++) {
        int idx = base + i * 4;
        float4 pn;
        pn.x = r[i].x + beta * p[i].x;
        pn.y = r[i].y + beta * p[i].y;
        pn.z = r[i].z + beta * p[i].z;
        pn.w = r[i].w + beta * p[i].w;
        *(float4*)&g_p[idx] = pn;
    }
}

// ---------------------------------------------------------------------------
extern "C" void kernel_launch(void* const* d_in, const int* in_sizes, int n_in,
                              void* d_out, int out_size) {
    const float* x = (const float*)d_in[0];
    const float* t = (const float*)d_in[1];
    const float* mu = (const float*)d_in[2];
    const float* cov = (const float*)d_in[3];
    float* out = (float*)d_out;

    init_kernel<<<BATCH, 256>>>(x, t, mu);
    prep_c_kernel<<<DD, 256>>>(cov);
    dim3 ggrid(DD / 64, BATCH / 64, SPLITK);  // (8, 8, 2) = 128 CTAs
    for (int it = 0; it < NITER - 1; it++) {
        gemm_mma_kernel<<<ggrid, 128>>>();
        cg_update_kernel<false><<<BATCH / 4, 256>>>(nullptr);
    }
    gemm_mma_kernel<<<ggrid, 128>>>();
    cg_update_kernel<true><<<BATCH / 4, 256>>>(out);
}